// round 2
// baseline (speedup 1.0000x reference)
#include <cuda_runtime.h>

// ---------------------------------------------------------------------------
// Problem constants
//   B=4096, FEAT=512, EMB=64, HID=1024, NUM_CLASSES=64, LIB=256, OUT_J=256
// Pipeline:
//   all_state[b] = concat(state[b], embed_table[option[b]])        [4096,576]
//   H  = relu(all_state @ [Wx1 | Wy1] + [bx1|by1])                 [4096,2048]
//   cls = H_x @ Wx2 + bx2 ; H_y @ Wy2 + by2                        [4096,512]
//   out_X = cls_X @ noise_lib_X                                    [4096,256]
//   out_Y[b] = cls_Y[b] @ noise_lib_Y[option[b]]                   [4096,256]
// ---------------------------------------------------------------------------

// Scratch (allocation-free rule: __device__ globals)
__device__ float g_H[4096 * 2048];     // H_x cols [0,1024), H_y cols [1024,2048)
__device__ float g_cls[4096 * 512];    // cls_X cols [0,256), cls_Y cols [256,512)
__device__ int   g_opt[4096];
__device__ int   g_offsets[65];
__device__ int   g_cursor[64];
__device__ int   g_perm[4096];

// ---------------------------------------------------------------------------
// K1: decode option (int64 or int32) + histogram + prefix sums. One block.
// Detection: view buffer as int32. If input is int64, every odd word is the
// high half of a value in [0,64) -> 0. If int32, odd words are random options
// (prob of all-zero ~ (1/64)^2048 ~ 0). Both reads stay within 4096 words,
// valid for either dtype.
// ---------------------------------------------------------------------------
__global__ void k_prep(const int* __restrict__ opt_raw) {
    __shared__ int s_counts[64];
    __shared__ int s_flag;
    const int tid = threadIdx.x;
    if (tid == 0) s_flag = 0;
    if (tid < 64) s_counts[tid] = 0;
    __syncthreads();
    int nz = 0;
    for (int w = 1 + 2 * tid; w < 4096; w += 512) nz |= opt_raw[w];
    if (nz) atomicOr(&s_flag, 1);
    __syncthreads();
    const bool is64 = (s_flag == 0);
    for (int i = tid; i < 4096; i += 256) {
        int v = is64 ? opt_raw[2 * i] : opt_raw[i];
        g_opt[i] = v;
        atomicAdd(&s_counts[v], 1);
    }
    __syncthreads();
    if (tid == 0) {
        int acc = 0;
        for (int c = 0; c < 64; c++) {
            g_offsets[c] = acc;
            g_cursor[c]  = acc;
            acc += s_counts[c];
        }
        g_offsets[64] = acc;
    }
}

// K2: scatter row indices into per-option buckets (order within bucket is
// nondeterministic, but every row's output is computed independently, so the
// final output is deterministic).
__global__ void k_scatter() {
    const int i = blockIdx.x * 256 + threadIdx.x;
    if (i < 4096) {
        const int v = g_opt[i];
        const int p = atomicAdd(&g_cursor[v], 1);
        g_perm[p] = i;
    }
}

// ---------------------------------------------------------------------------
// GEMM1: [4096 x 576] @ [576 x 2048] -> relu -> g_H
// A is virtual: cols [0,512) from state, cols [512,576) from embed_table[opt].
// 128x128x8 tiles, 256 threads, 8x8 microtile.
// ---------------------------------------------------------------------------
__global__ __launch_bounds__(256) void k_gemm1(
    const float* __restrict__ state, const float* __restrict__ embed,
    const float* __restrict__ Wx1, const float* __restrict__ bx1,
    const float* __restrict__ Wy1, const float* __restrict__ by1) {
    const int bm  = blockIdx.y * 128;
    const int bnG = blockIdx.x * 128;
    const float* W; const float* bias; int bn;
    if (bnG < 1024) { W = Wx1; bias = bx1; bn = bnG; }
    else            { W = Wy1; bias = by1; bn = bnG - 1024; }

    __shared__ float As[8][132];  // padded: conflict-free transposed stores
    __shared__ float Bs[8][128];

    const int tid = threadIdx.x;
    const int tr = tid >> 4, tc = tid & 15;
    const int aRow = tid >> 1;
    const int aK4  = (tid & 1) * 4;
    const int bRow = tid >> 5;
    const int bCol = (tid & 31) * 4;

    const int grow = bm + aRow;
    const float* aState = state + (size_t)grow * 512;
    const float* aEmb   = embed + g_opt[grow] * 64;

    float acc[8][8];
    #pragma unroll
    for (int i = 0; i < 8; i++)
        #pragma unroll
        for (int j = 0; j < 8; j++) acc[i][j] = 0.f;

    for (int k0 = 0; k0 < 576; k0 += 8) {
        const int gk = k0 + aK4;
        float4 av = (gk < 512) ? *(const float4*)(aState + gk)
                               : *(const float4*)(aEmb + (gk - 512));
        As[aK4 + 0][aRow] = av.x; As[aK4 + 1][aRow] = av.y;
        As[aK4 + 2][aRow] = av.z; As[aK4 + 3][aRow] = av.w;
        *(float4*)&Bs[bRow][bCol] =
            *(const float4*)(W + (size_t)(k0 + bRow) * 1024 + bn + bCol);
        __syncthreads();
        #pragma unroll
        for (int k = 0; k < 8; k++) {
            float4 a0 = *(const float4*)&As[k][tr * 8];
            float4 a1 = *(const float4*)&As[k][tr * 8 + 4];
            float4 b0 = *(const float4*)&Bs[k][tc * 8];
            float4 b1 = *(const float4*)&Bs[k][tc * 8 + 4];
            float ra[8] = {a0.x, a0.y, a0.z, a0.w, a1.x, a1.y, a1.z, a1.w};
            float rb[8] = {b0.x, b0.y, b0.z, b0.w, b1.x, b1.y, b1.z, b1.w};
            #pragma unroll
            for (int i = 0; i < 8; i++)
                #pragma unroll
                for (int j = 0; j < 8; j++)
                    acc[i][j] = fmaf(ra[i], rb[j], acc[i][j]);
        }
        __syncthreads();
    }
    float bv[8];
    #pragma unroll
    for (int j = 0; j < 8; j++) bv[j] = bias[bn + tc * 8 + j];
    #pragma unroll
    for (int i = 0; i < 8; i++) {
        const int row = bm + tr * 8 + i;
        float4 o0, o1;
        o0.x = fmaxf(acc[i][0] + bv[0], 0.f); o0.y = fmaxf(acc[i][1] + bv[1], 0.f);
        o0.z = fmaxf(acc[i][2] + bv[2], 0.f); o0.w = fmaxf(acc[i][3] + bv[3], 0.f);
        o1.x = fmaxf(acc[i][4] + bv[4], 0.f); o1.y = fmaxf(acc[i][5] + bv[5], 0.f);
        o1.z = fmaxf(acc[i][6] + bv[6], 0.f); o1.w = fmaxf(acc[i][7] + bv[7], 0.f);
        float* dst = g_H + (size_t)row * 2048 + bnG + tc * 8;
        *(float4*)dst = o0;
        *(float4*)(dst + 4) = o1;
    }
}

// ---------------------------------------------------------------------------
// GEMM2: cls_X = H_x @ Wx2 + bx2 ; cls_Y = H_y @ Wy2 + by2   (K=1024, no relu)
// ---------------------------------------------------------------------------
__global__ __launch_bounds__(256) void k_gemm2(
    const float* __restrict__ Wx2, const float* __restrict__ bx2,
    const float* __restrict__ Wy2, const float* __restrict__ by2) {
    const int bm  = blockIdx.y * 128;
    const int bnG = blockIdx.x * 128;  // 0..511
    const float* W; const float* bias; int bn; int aOff;
    if (bnG < 256) { W = Wx2; bias = bx2; bn = bnG;       aOff = 0;    }
    else           { W = Wy2; bias = by2; bn = bnG - 256; aOff = 1024; }

    __shared__ float As[8][132];
    __shared__ float Bs[8][128];

    const int tid = threadIdx.x;
    const int tr = tid >> 4, tc = tid & 15;
    const int aRow = tid >> 1;
    const int aK4  = (tid & 1) * 4;
    const int bRow = tid >> 5;
    const int bCol = (tid & 31) * 4;

    const float* aPtr = g_H + (size_t)(bm + aRow) * 2048 + aOff;

    float acc[8][8];
    #pragma unroll
    for (int i = 0; i < 8; i++)
        #pragma unroll
        for (int j = 0; j < 8; j++) acc[i][j] = 0.f;

    for (int k0 = 0; k0 < 1024; k0 += 8) {
        float4 av = *(const float4*)(aPtr + k0 + aK4);
        As[aK4 + 0][aRow] = av.x; As[aK4 + 1][aRow] = av.y;
        As[aK4 + 2][aRow] = av.z; As[aK4 + 3][aRow] = av.w;
        *(float4*)&Bs[bRow][bCol] =
            *(const float4*)(W + (size_t)(k0 + bRow) * 256 + bn + bCol);
        __syncthreads();
        #pragma unroll
        for (int k = 0; k < 8; k++) {
            float4 a0 = *(const float4*)&As[k][tr * 8];
            float4 a1 = *(const float4*)&As[k][tr * 8 + 4];
            float4 b0 = *(const float4*)&Bs[k][tc * 8];
            float4 b1 = *(const float4*)&Bs[k][tc * 8 + 4];
            float ra[8] = {a0.x, a0.y, a0.z, a0.w, a1.x, a1.y, a1.z, a1.w};
            float rb[8] = {b0.x, b0.y, b0.z, b0.w, b1.x, b1.y, b1.z, b1.w};
            #pragma unroll
            for (int i = 0; i < 8; i++)
                #pragma unroll
                for (int j = 0; j < 8; j++)
                    acc[i][j] = fmaf(ra[i], rb[j], acc[i][j]);
        }
        __syncthreads();
    }
    float bv[8];
    #pragma unroll
    for (int j = 0; j < 8; j++) bv[j] = bias[bn + tc * 8 + j];
    #pragma unroll
    for (int i = 0; i < 8; i++) {
        const int row = bm + tr * 8 + i;
        float4 o0 = make_float4(acc[i][0] + bv[0], acc[i][1] + bv[1],
                                acc[i][2] + bv[2], acc[i][3] + bv[3]);
        float4 o1 = make_float4(acc[i][4] + bv[4], acc[i][5] + bv[5],
                                acc[i][6] + bv[6], acc[i][7] + bv[7]);
        float* dst = g_cls + (size_t)row * 512 + bnG + tc * 8;
        *(float4*)dst = o0;
        *(float4*)(dst + 4) = o1;
    }
}

// ---------------------------------------------------------------------------
// GEMM_X: out_X = cls_X @ noise_lib_X   (M=4096, N=256, K=256)
// ---------------------------------------------------------------------------
__global__ __launch_bounds__(256) void k_gemmx(
    const float* __restrict__ NX, float* __restrict__ out) {
    const int bm = blockIdx.y * 128;
    const int bn = blockIdx.x * 128;

    __shared__ float As[8][132];
    __shared__ float Bs[8][128];

    const int tid = threadIdx.x;
    const int tr = tid >> 4, tc = tid & 15;
    const int aRow = tid >> 1;
    const int aK4  = (tid & 1) * 4;
    const int bRow = tid >> 5;
    const int bCol = (tid & 31) * 4;

    const float* aPtr = g_cls + (size_t)(bm + aRow) * 512;  // cls_X: cols [0,256)

    float acc[8][8];
    #pragma unroll
    for (int i = 0; i < 8; i++)
        #pragma unroll
        for (int j = 0; j < 8; j++) acc[i][j] = 0.f;

    for (int k0 = 0; k0 < 256; k0 += 8) {
        float4 av = *(const float4*)(aPtr + k0 + aK4);
        As[aK4 + 0][aRow] = av.x; As[aK4 + 1][aRow] = av.y;
        As[aK4 + 2][aRow] = av.z; As[aK4 + 3][aRow] = av.w;
        *(float4*)&Bs[bRow][bCol] =
            *(const float4*)(NX + (size_t)(k0 + bRow) * 256 + bn + bCol);
        __syncthreads();
        #pragma unroll
        for (int k = 0; k < 8; k++) {
            float4 a0 = *(const float4*)&As[k][tr * 8];
            float4 a1 = *(const float4*)&As[k][tr * 8 + 4];
            float4 b0 = *(const float4*)&Bs[k][tc * 8];
            float4 b1 = *(const float4*)&Bs[k][tc * 8 + 4];
            float ra[8] = {a0.x, a0.y, a0.z, a0.w, a1.x, a1.y, a1.z, a1.w};
            float rb[8] = {b0.x, b0.y, b0.z, b0.w, b1.x, b1.y, b1.z, b1.w};
            #pragma unroll
            for (int i = 0; i < 8; i++)
                #pragma unroll
                for (int j = 0; j < 8; j++)
                    acc[i][j] = fmaf(ra[i], rb[j], acc[i][j]);
        }
        __syncthreads();
    }
    #pragma unroll
    for (int i = 0; i < 8; i++) {
        const int row = bm + tr * 8 + i;
        float4 o0 = make_float4(acc[i][0], acc[i][1], acc[i][2], acc[i][3]);
        float4 o1 = make_float4(acc[i][4], acc[i][5], acc[i][6], acc[i][7]);
        float* dst = out + (size_t)row * 256 + bn + tc * 8;
        *(float4*)dst = o0;
        *(float4*)(dst + 4) = o1;
    }
}

// ---------------------------------------------------------------------------
// GEMM_Y (grouped): for each option c, rows perm[offsets[c]..offsets[c+1])
// out_Y[r] = cls_Y[r] @ noise_lib_Y[c].  Tiles 64 rows x 128 cols, K=256.
// Each NY[c] tile is streamed once per block (2 col-tiles) -> ~34 MB L2 reads
// instead of ~1 GB for per-row matvecs.
// ---------------------------------------------------------------------------
__global__ __launch_bounds__(256) void k_gemmy(
    const float* __restrict__ NY, float* __restrict__ outY) {
    const int c  = blockIdx.y;
    const int bn = blockIdx.x * 128;
    const int start = g_offsets[c], end = g_offsets[c + 1];
    const float* Bmat = NY + (size_t)c * 65536;

    __shared__ float As[8][68];
    __shared__ float Bs[8][128];
    __shared__ int rowIdx[64];

    const int tid = threadIdx.x;
    const int tr = tid >> 4, tc = tid & 15;  // rows tr*4..+3, cols tc*8..+7
    const int bRow = tid >> 5, bCol = (tid & 31) * 4;
    const int ar = tid >> 1, ak = (tid & 1) * 4;

    for (int chunk = start; chunk < end; chunk += 64) {
        if (tid < 64) rowIdx[tid] = (chunk + tid < end) ? g_perm[chunk + tid] : -1;
        __syncthreads();
        float acc[4][8];
        #pragma unroll
        for (int i = 0; i < 4; i++)
            #pragma unroll
            for (int j = 0; j < 8; j++) acc[i][j] = 0.f;

        for (int k0 = 0; k0 < 256; k0 += 8) {
            if (tid < 128) {
                const int r = rowIdx[ar];
                float4 av = make_float4(0.f, 0.f, 0.f, 0.f);
                if (r >= 0)
                    av = *(const float4*)(g_cls + (size_t)r * 512 + 256 + k0 + ak);
                As[ak + 0][ar] = av.x; As[ak + 1][ar] = av.y;
                As[ak + 2][ar] = av.z; As[ak + 3][ar] = av.w;
            }
            *(float4*)&Bs[bRow][bCol] =
                *(const float4*)(Bmat + (size_t)(k0 + bRow) * 256 + bn + bCol);
            __syncthreads();
            #pragma unroll
            for (int k = 0; k < 8; k++) {
                float4 a0 = *(const float4*)&As[k][tr * 4];
                float4 b0 = *(const float4*)&Bs[k][tc * 8];
                float4 b1 = *(const float4*)&Bs[k][tc * 8 + 4];
                float ra[4] = {a0.x, a0.y, a0.z, a0.w};
                float rb[8] = {b0.x, b0.y, b0.z, b0.w, b1.x, b1.y, b1.z, b1.w};
                #pragma unroll
                for (int i = 0; i < 4; i++)
                    #pragma unroll
                    for (int j = 0; j < 8; j++)
                        acc[i][j] = fmaf(ra[i], rb[j], acc[i][j]);
            }
            __syncthreads();
        }
        #pragma unroll
        for (int i = 0; i < 4; i++) {
            const int r = rowIdx[tr * 4 + i];
            if (r >= 0) {
                float4 o0 = make_float4(acc[i][0], acc[i][1], acc[i][2], acc[i][3]);
                float4 o1 = make_float4(acc[i][4], acc[i][5], acc[i][6], acc[i][7]);
                float* dst = outY + (size_t)r * 256 + bn + tc * 8;
                *(float4*)dst = o0;
                *(float4*)(dst + 4) = o1;
            }
        }
        __syncthreads();  // before rowIdx is overwritten next chunk
    }
}

// ---------------------------------------------------------------------------
// Launch. Inputs (metadata order):
//  0 state, 1 option, 2 embed_table, 3 Wx1, 4 bx1, 5 Wx2, 6 bx2,
//  7 Wy1, 8 by1, 9 Wy2, 10 by2, 11 noise_lib_X, 12 noise_lib_Y
// Output: [noise_X (4096*256) | noise_Y (4096*256)] fp32
// ---------------------------------------------------------------------------
extern "C" void kernel_launch(void* const* d_in, const int* in_sizes, int n_in,
                              void* d_out, int out_size) {
    const float* state  = (const float*)d_in[0];
    const int*   optraw = (const int*)d_in[1];
    const float* embed  = (const float*)d_in[2];
    const float* Wx1 = (const float*)d_in[3];
    const float* bx1 = (const float*)d_in[4];
    const float* Wx2 = (const float*)d_in[5];
    const float* bx2 = (const float*)d_in[6];
    const float* Wy1 = (const float*)d_in[7];
    const float* by1 = (const float*)d_in[8];
    const float* Wy2 = (const float*)d_in[9];
    const float* by2 = (const float*)d_in[10];
    const float* NX  = (const float*)d_in[11];
    const float* NY  = (const float*)d_in[12];
    float* out = (float*)d_out;

    k_prep<<<1, 256>>>(optraw);
    k_scatter<<<16, 256>>>();
    k_gemm1<<<dim3(16, 32), 256>>>(state, embed, Wx1, bx1, Wy1, by1);
    k_gemm2<<<dim3(4, 32), 256>>>(Wx2, bx2, Wy2, by2);
    k_gemmx<<<dim3(2, 32), 256>>>(NX, out);
    k_gemmy<<<dim3(2, 64), 256>>>(NY, out + (size_t)4096 * 256);
}

// round 5
// speedup vs baseline: 2.6844x; 2.6844x over previous
#include <cuda_runtime.h>

// ---------------------------------------------------------------------------
// B=4096, FEAT=512, EMB=64, HID=1024, NUM_CLASSES=64, LIB=256, OUT_J=256
//   all_state = concat(state, embed[option])            [4096,576]
//   H  = relu(all_state @ [Wx1|Wy1] + b)                [4096,2048]
//   cls = H_x @ Wx2 + bx2 ; H_y @ Wy2 + by2             [4096,512]
//   out_X = cls_X @ NX ; out_Y[b] = cls_Y[b] @ NY[opt]  [4096,256] each
// All GEMMs on tensor pipe: mma.sync m16n8k8 tf32, fp32 accum.
// ---------------------------------------------------------------------------

__device__ float g_H[4096 * 2048];
__device__ float g_cls[4096 * 512];
__device__ int   g_opt[4096];
__device__ int   g_offsets[65];
__device__ int   g_cursor[64];
__device__ int   g_perm[4096];

static __device__ __forceinline__ float f2tf(float x) {
    unsigned r;
    asm("cvt.rna.tf32.f32 %0, %1;" : "=r"(r) : "f"(x));
    return __uint_as_float(r);
}

static __device__ __forceinline__ void mma8(float* c,
    unsigned a0, unsigned a1, unsigned a2, unsigned a3,
    unsigned b0, unsigned b1) {
    asm volatile(
        "mma.sync.aligned.m16n8k8.row.col.f32.tf32.tf32.f32 "
        "{%0,%1,%2,%3},{%4,%5,%6,%7},{%8,%9},{%0,%1,%2,%3};"
        : "+f"(c[0]), "+f"(c[1]), "+f"(c[2]), "+f"(c[3])
        : "r"(a0), "r"(a1), "r"(a2), "r"(a3), "r"(b0), "r"(b1));
}

// Shared tile compute: A smem [rows][20] row-major, B smem [16][136] row-major.
// Both strides chosen conflict-free for the fragment access patterns.
// acc[mf*NF+nf][4]; K chunk = 16 (two k8 steps).
template <int MF, int NF>
static __device__ __forceinline__ void tile_mma(
    const float* __restrict__ As, const float* __restrict__ Bs,
    int mOff, int nOff, float acc[][4]) {
    const int lane = threadIdx.x & 31;
    const int g = lane >> 2, t = lane & 3;
    #pragma unroll
    for (int ks = 0; ks < 16; ks += 8) {
        unsigned a[MF][4];
        #pragma unroll
        for (int mf = 0; mf < MF; mf++) {
            const float* ap = As + (mOff + mf * 16 + g) * 20 + ks + t;
            a[mf][0] = __float_as_uint(ap[0]);
            a[mf][1] = __float_as_uint(ap[8 * 20]);
            a[mf][2] = __float_as_uint(ap[4]);
            a[mf][3] = __float_as_uint(ap[8 * 20 + 4]);
        }
        #pragma unroll
        for (int nf = 0; nf < NF; nf++) {
            const float* bp = Bs + (ks + t) * 136 + nOff + nf * 8 + g;
            unsigned b0 = __float_as_uint(bp[0]);
            unsigned b1 = __float_as_uint(bp[4 * 136]);
            #pragma unroll
            for (int mf = 0; mf < MF; mf++)
                mma8(acc[mf * NF + nf], a[mf][0], a[mf][1], a[mf][2], a[mf][3], b0, b1);
        }
    }
}

// ---------------------------------------------------------------------------
// K1: decode option (int64 vs int32) + histogram + offsets. One block.
// ---------------------------------------------------------------------------
__global__ void k_prep(const int* __restrict__ opt_raw) {
    __shared__ int s_counts[64];
    __shared__ int s_flag;
    const int tid = threadIdx.x;
    if (tid == 0) s_flag = 0;
    if (tid < 64) s_counts[tid] = 0;
    __syncthreads();
    int nz = 0;
    for (int w = 1 + 2 * tid; w < 4096; w += 512) nz |= opt_raw[w];
    if (nz) atomicOr(&s_flag, 1);
    __syncthreads();
    const bool is64 = (s_flag == 0);
    for (int i = tid; i < 4096; i += 256) {
        int v = is64 ? opt_raw[2 * i] : opt_raw[i];
        g_opt[i] = v;
        atomicAdd(&s_counts[v], 1);
    }
    __syncthreads();
    if (tid == 0) {
        int acc = 0;
        for (int c = 0; c < 64; c++) {
            g_offsets[c] = acc;
            g_cursor[c]  = acc;
            acc += s_counts[c];
        }
        g_offsets[64] = acc;
    }
}

__global__ void k_scatter() {
    const int i = blockIdx.x * 256 + threadIdx.x;
    if (i < 4096) {
        const int v = g_opt[i];
        const int p = atomicAdd(&g_cursor[v], 1);
        g_perm[p] = i;
    }
}

// ---------------------------------------------------------------------------
// GEMM1: [4096x576] @ [576x2048] + bias, relu -> g_H. Tensor tf32.
// 128x128 block, 8 warps (4m x 2n), warp tile 32x64.
// ---------------------------------------------------------------------------
__global__ __launch_bounds__(256, 2) void k_gemm1(
    const float* __restrict__ state, const float* __restrict__ embed,
    const float* __restrict__ Wx1, const float* __restrict__ bx1,
    const float* __restrict__ Wy1, const float* __restrict__ by1) {
    const int bm = blockIdx.y * 128, bnG = blockIdx.x * 128;
    const float* W; const float* bias; int bn;
    if (bnG < 1024) { W = Wx1; bias = bx1; bn = bnG; }
    else            { W = Wy1; bias = by1; bn = bnG - 1024; }

    __shared__ float As[2][128 * 20];
    __shared__ float Bs[2][16 * 136];

    const int tid = threadIdx.x;
    const int warp = tid >> 5;
    const int mOff = (warp >> 1) * 32, nOff = (warp & 1) * 64;
    const int aRow = tid >> 1, aC = (tid & 1) * 8;
    const int bRow = tid >> 4, bC = (tid & 15) * 8;

    const int grow = bm + aRow;
    const float* aState = state + (size_t)grow * 512;
    const float* aEmb   = embed + g_opt[grow] * 64;

    float acc[16][4];
    #pragma unroll
    for (int i = 0; i < 16; i++)
        #pragma unroll
        for (int j = 0; j < 4; j++) acc[i][j] = 0.f;

    float4 pa0, pa1, pb0, pb1;
    auto fetch = [&](int k0) {
        const int gk = k0 + aC;
        const float* sa = (gk < 512) ? (aState + gk) : (aEmb + (gk - 512));
        pa0 = *(const float4*)sa; pa1 = *(const float4*)(sa + 4);
        const float* sb = W + (size_t)(k0 + bRow) * 1024 + bn + bC;
        pb0 = *(const float4*)sb; pb1 = *(const float4*)(sb + 4);
    };
    auto deposit = [&](int buf) {
        float* ad = &As[buf][aRow * 20 + aC];
        ad[0] = f2tf(pa0.x); ad[1] = f2tf(pa0.y); ad[2] = f2tf(pa0.z); ad[3] = f2tf(pa0.w);
        ad[4] = f2tf(pa1.x); ad[5] = f2tf(pa1.y); ad[6] = f2tf(pa1.z); ad[7] = f2tf(pa1.w);
        float* bd = &Bs[buf][bRow * 136 + bC];
        bd[0] = f2tf(pb0.x); bd[1] = f2tf(pb0.y); bd[2] = f2tf(pb0.z); bd[3] = f2tf(pb0.w);
        bd[4] = f2tf(pb1.x); bd[5] = f2tf(pb1.y); bd[6] = f2tf(pb1.z); bd[7] = f2tf(pb1.w);
    };

    fetch(0); deposit(0); __syncthreads();
    const int NC = 36;
    for (int c = 0; c < NC; c++) {
        if (c + 1 < NC) fetch((c + 1) * 16);
        tile_mma<2, 8>(As[c & 1], Bs[c & 1], mOff, nOff, acc);
        if (c + 1 < NC) deposit((c + 1) & 1);
        __syncthreads();
    }

    const int lane = tid & 31, g = lane >> 2, t = lane & 3;
    #pragma unroll
    for (int mf = 0; mf < 2; mf++)
        #pragma unroll
        for (int nf = 0; nf < 8; nf++) {
            const float* ca = acc[mf * 8 + nf];
            const int ncol = nOff + nf * 8 + 2 * t;
            const float bv0 = bias[bn + ncol], bv1 = bias[bn + ncol + 1];
            const int r0 = bm + mOff + mf * 16 + g;
            float2 o;
            o.x = fmaxf(ca[0] + bv0, 0.f); o.y = fmaxf(ca[1] + bv1, 0.f);
            *(float2*)&g_H[(size_t)r0 * 2048 + bnG + ncol] = o;
            o.x = fmaxf(ca[2] + bv0, 0.f); o.y = fmaxf(ca[3] + bv1, 0.f);
            *(float2*)&g_H[(size_t)(r0 + 8) * 2048 + bnG + ncol] = o;
        }
}

// ---------------------------------------------------------------------------
// GEMM2: cls = H @ [Wx2|Wy2] + bias (K=1024). Tensor tf32.
// ---------------------------------------------------------------------------
__global__ __launch_bounds__(256, 2) void k_gemm2(
    const float* __restrict__ Wx2, const float* __restrict__ bx2,
    const float* __restrict__ Wy2, const float* __restrict__ by2) {
    const int bm = blockIdx.y * 128, bnG = blockIdx.x * 128;
    const float* W; const float* bias; int bn, aOff;
    if (bnG < 256) { W = Wx2; bias = bx2; bn = bnG;       aOff = 0;    }
    else           { W = Wy2; bias = by2; bn = bnG - 256; aOff = 1024; }

    __shared__ float As[2][128 * 20];
    __shared__ float Bs[2][16 * 136];

    const int tid = threadIdx.x;
    const int warp = tid >> 5;
    const int mOff = (warp >> 1) * 32, nOff = (warp & 1) * 64;
    const int aRow = tid >> 1, aC = (tid & 1) * 8;
    const int bRow = tid >> 4, bC = (tid & 15) * 8;

    const float* aPtr = g_H + (size_t)(bm + aRow) * 2048 + aOff;

    float acc[16][4];
    #pragma unroll
    for (int i = 0; i < 16; i++)
        #pragma unroll
        for (int j = 0; j < 4; j++) acc[i][j] = 0.f;

    float4 pa0, pa1, pb0, pb1;
    auto fetch = [&](int k0) {
        const float* sa = aPtr + k0 + aC;
        pa0 = *(const float4*)sa; pa1 = *(const float4*)(sa + 4);
        const float* sb = W + (size_t)(k0 + bRow) * 256 + bn + bC;
        pb0 = *(const float4*)sb; pb1 = *(const float4*)(sb + 4);
    };
    auto deposit = [&](int buf) {
        float* ad = &As[buf][aRow * 20 + aC];
        ad[0] = f2tf(pa0.x); ad[1] = f2tf(pa0.y); ad[2] = f2tf(pa0.z); ad[3] = f2tf(pa0.w);
        ad[4] = f2tf(pa1.x); ad[5] = f2tf(pa1.y); ad[6] = f2tf(pa1.z); ad[7] = f2tf(pa1.w);
        float* bd = &Bs[buf][bRow * 136 + bC];
        bd[0] = f2tf(pb0.x); bd[1] = f2tf(pb0.y); bd[2] = f2tf(pb0.z); bd[3] = f2tf(pb0.w);
        bd[4] = f2tf(pb1.x); bd[5] = f2tf(pb1.y); bd[6] = f2tf(pb1.z); bd[7] = f2tf(pb1.w);
    };

    fetch(0); deposit(0); __syncthreads();
    const int NC = 64;
    for (int c = 0; c < NC; c++) {
        if (c + 1 < NC) fetch((c + 1) * 16);
        tile_mma<2, 8>(As[c & 1], Bs[c & 1], mOff, nOff, acc);
        if (c + 1 < NC) deposit((c + 1) & 1);
        __syncthreads();
    }

    const int lane = tid & 31, g = lane >> 2, t = lane & 3;
    #pragma unroll
    for (int mf = 0; mf < 2; mf++)
        #pragma unroll
        for (int nf = 0; nf < 8; nf++) {
            const float* ca = acc[mf * 8 + nf];
            const int ncol = nOff + nf * 8 + 2 * t;
            const float bv0 = bias[bn + ncol], bv1 = bias[bn + ncol + 1];
            const int r0 = bm + mOff + mf * 16 + g;
            *(float2*)&g_cls[(size_t)r0 * 512 + bnG + ncol] =
                make_float2(ca[0] + bv0, ca[1] + bv1);
            *(float2*)&g_cls[(size_t)(r0 + 8) * 512 + bnG + ncol] =
                make_float2(ca[2] + bv0, ca[3] + bv1);
        }
}

// ---------------------------------------------------------------------------
// GEMM_X: out_X = cls_X @ NX (M=4096,N=256,K=256). Tensor tf32.
// ---------------------------------------------------------------------------
__global__ __launch_bounds__(256, 2) void k_gemmx(
    const float* __restrict__ NX, float* __restrict__ out) {
    const int bm = blockIdx.y * 128, bn = blockIdx.x * 128;

    __shared__ float As[2][128 * 20];
    __shared__ float Bs[2][16 * 136];

    const int tid = threadIdx.x;
    const int warp = tid >> 5;
    const int mOff = (warp >> 1) * 32, nOff = (warp & 1) * 64;
    const int aRow = tid >> 1, aC = (tid & 1) * 8;
    const int bRow = tid >> 4, bC = (tid & 15) * 8;

    const float* aPtr = g_cls + (size_t)(bm + aRow) * 512;

    float acc[16][4];
    #pragma unroll
    for (int i = 0; i < 16; i++)
        #pragma unroll
        for (int j = 0; j < 4; j++) acc[i][j] = 0.f;

    float4 pa0, pa1, pb0, pb1;
    auto fetch = [&](int k0) {
        const float* sa = aPtr + k0 + aC;
        pa0 = *(const float4*)sa; pa1 = *(const float4*)(sa + 4);
        const float* sb = NX + (size_t)(k0 + bRow) * 256 + bn + bC;
        pb0 = *(const float4*)sb; pb1 = *(const float4*)(sb + 4);
    };
    auto deposit = [&](int buf) {
        float* ad = &As[buf][aRow * 20 + aC];
        ad[0] = f2tf(pa0.x); ad[1] = f2tf(pa0.y); ad[2] = f2tf(pa0.z); ad[3] = f2tf(pa0.w);
        ad[4] = f2tf(pa1.x); ad[5] = f2tf(pa1.y); ad[6] = f2tf(pa1.z); ad[7] = f2tf(pa1.w);
        float* bd = &Bs[buf][bRow * 136 + bC];
        bd[0] = f2tf(pb0.x); bd[1] = f2tf(pb0.y); bd[2] = f2tf(pb0.z); bd[3] = f2tf(pb0.w);
        bd[4] = f2tf(pb1.x); bd[5] = f2tf(pb1.y); bd[6] = f2tf(pb1.z); bd[7] = f2tf(pb1.w);
    };

    fetch(0); deposit(0); __syncthreads();
    const int NC = 16;
    for (int c = 0; c < NC; c++) {
        if (c + 1 < NC) fetch((c + 1) * 16);
        tile_mma<2, 8>(As[c & 1], Bs[c & 1], mOff, nOff, acc);
        if (c + 1 < NC) deposit((c + 1) & 1);
        __syncthreads();
    }

    const int lane = tid & 31, g = lane >> 2, t = lane & 3;
    #pragma unroll
    for (int mf = 0; mf < 2; mf++)
        #pragma unroll
        for (int nf = 0; nf < 8; nf++) {
            const float* ca = acc[mf * 8 + nf];
            const int ncol = nOff + nf * 8 + 2 * t;
            const int r0 = bm + mOff + mf * 16 + g;
            *(float2*)&out[(size_t)r0 * 256 + bn + ncol] = make_float2(ca[0], ca[1]);
            *(float2*)&out[(size_t)(r0 + 8) * 256 + bn + ncol] = make_float2(ca[2], ca[3]);
        }
}

// ---------------------------------------------------------------------------
// GEMM_Y (grouped by option): 64-row chunks per class. Tensor tf32.
// Block 64x128: 8 warps (2m x 4n), warp tile 32x32.
// ---------------------------------------------------------------------------
__global__ __launch_bounds__(256, 2) void k_gemmy(
    const float* __restrict__ NY, float* __restrict__ outY) {
    const int cls = blockIdx.y;
    const int bn  = blockIdx.x * 128;
    const int start = g_offsets[cls], end = g_offsets[cls + 1];
    const float* Bmat = NY + (size_t)cls * 65536;

    __shared__ float As[2][64 * 20];
    __shared__ float Bs[2][16 * 136];
    __shared__ int rowIdx[64];

    const int tid = threadIdx.x;
    const int warp = tid >> 5;
    const int mOff = (warp >> 2) * 32, nOff = (warp & 3) * 32;
    const int aRow = tid >> 2, aC = (tid & 3) * 4;
    const int bRow = tid >> 4, bC = (tid & 15) * 8;
    const int lane = tid & 31, g = lane >> 2, t = lane & 3;

    for (int chunk = start; chunk < end; chunk += 64) {
        if (tid < 64) rowIdx[tid] = (chunk + tid < end) ? g_perm[chunk + tid] : -1;
        __syncthreads();

        float acc[8][4];
        #pragma unroll
        for (int i = 0; i < 8; i++)
            #pragma unroll
            for (int j = 0; j < 4; j++) acc[i][j] = 0.f;

        float4 pa, pb0, pb1;
        const int myRow = rowIdx[aRow];
        auto fetch = [&](int k0) {
            pa = make_float4(0.f, 0.f, 0.f, 0.f);
            if (myRow >= 0)
                pa = *(const float4*)(g_cls + (size_t)myRow * 512 + 256 + k0 + aC);
            const float* sb = Bmat + (size_t)(k0 + bRow) * 256 + bn + bC;
            pb0 = *(const float4*)sb; pb1 = *(const float4*)(sb + 4);
        };
        auto deposit = [&](int buf) {
            float* ad = &As[buf][aRow * 20 + aC];
            ad[0] = f2tf(pa.x); ad[1] = f2tf(pa.y); ad[2] = f2tf(pa.z); ad[3] = f2tf(pa.w);
            float* bd = &Bs[buf][bRow * 136 + bC];
            bd[0] = f2tf(pb0.x); bd[1] = f2tf(pb0.y); bd[2] = f2tf(pb0.z); bd[3] = f2tf(pb0.w);
            bd[4] = f2tf(pb1.x); bd[5] = f2tf(pb1.y); bd[6] = f2tf(pb1.z); bd[7] = f2tf(pb1.w);
        };

        fetch(0); deposit(0); __syncthreads();
        const int NC = 16;
        for (int c = 0; c < NC; c++) {
            if (c + 1 < NC) fetch((c + 1) * 16);
            tile_mma<2, 4>(As[c & 1], Bs[c & 1], mOff, nOff, acc);
            if (c + 1 < NC) deposit((c + 1) & 1);
            __syncthreads();
        }

        #pragma unroll
        for (int mf = 0; mf < 2; mf++)
            #pragma unroll
            for (int nf = 0; nf < 4; nf++) {
                const float* ca = acc[mf * 4 + nf];
                const int ncol = bn + nOff + nf * 8 + 2 * t;
                const int lr = mOff + mf * 16 + g;
                const int r0 = rowIdx[lr], r1 = rowIdx[lr + 8];
                if (r0 >= 0)
                    *(float2*)&outY[(size_t)r0 * 256 + ncol] = make_float2(ca[0], ca[1]);
                if (r1 >= 0)
                    *(float2*)&outY[(size_t)r1 * 256 + ncol] = make_float2(ca[2], ca[3]);
            }
        __syncthreads();  // protect rowIdx / smem before next chunk
    }
}

// ---------------------------------------------------------------------------
// Launch. Inputs: 0 state, 1 option, 2 embed, 3 Wx1, 4 bx1, 5 Wx2, 6 bx2,
// 7 Wy1, 8 by1, 9 Wy2, 10 by2, 11 NX, 12 NY. Output: [out_X | out_Y] fp32.
// ---------------------------------------------------------------------------
extern "C" void kernel_launch(void* const* d_in, const int* in_sizes, int n_in,
                              void* d_out, int out_size) {
    const float* state  = (const float*)d_in[0];
    const int*   optraw = (const int*)d_in[1];
    const float* embed  = (const float*)d_in[2];
    const float* Wx1 = (const float*)d_in[3];
    const float* bx1 = (const float*)d_in[4];
    const float* Wx2 = (const float*)d_in[5];
    const float* bx2 = (const float*)d_in[6];
    const float* Wy1 = (const float*)d_in[7];
    const float* by1 = (const float*)d_in[8];
    const float* Wy2 = (const float*)d_in[9];
    const float* by2 = (const float*)d_in[10];
    const float* NX  = (const float*)d_in[11];
    const float* NY  = (const float*)d_in[12];
    float* out = (float*)d_out;

    k_prep<<<1, 256>>>(optraw);
    k_scatter<<<16, 256>>>();
    k_gemm1<<<dim3(16, 32), 256>>>(state, embed, Wx1, bx1, Wy1, by1);
    k_gemm2<<<dim3(4, 32), 256>>>(Wx2, bx2, Wy2, by2);
    k_gemmx<<<dim3(2, 32), 256>>>(NX, out);
    k_gemmy<<<dim3(2, 64), 256>>>(NY, out + (size_t)4096 * 256);
}

// round 6
// speedup vs baseline: 2.8612x; 1.0659x over previous
#include <cuda_runtime.h>

// ---------------------------------------------------------------------------
// B=4096, FEAT=512, EMB=64, HID=1024, NUM_CLASSES=64, LIB=256, OUT_J=256
//   all_state = concat(state, embed[option])            [4096,576]
//   H  = relu(all_state @ [Wx1|Wy1] + b)                [4096,2048]
//   cls = H_x @ Wx2 + bx2 ; H_y @ Wy2 + by2             [4096,512]
//   out_X = cls_X @ NX ; out_Y[b] = cls_Y[b] @ NY[opt]  [4096,256] each
// Tensor pipe tf32 mma m16n8k8. cp.async 3-stage pipeline, ldmatrix A frags.
// ---------------------------------------------------------------------------

__device__ float g_H[4096 * 2048];
__device__ float g_cls[4096 * 512];
__device__ int   g_opt[4096];
__device__ int   g_offsets[65];
__device__ int   g_cursor[64];
__device__ int   g_perm[4096];

static __device__ __forceinline__ float f2tf(float x) {
    unsigned r;
    asm("cvt.rna.tf32.f32 %0, %1;" : "=r"(r) : "f"(x));
    return __uint_as_float(r);
}
static __device__ __forceinline__ unsigned cvt_tf_u(unsigned x) {
    unsigned r;
    asm("cvt.rna.tf32.f32 %0, %1;" : "=r"(r) : "f"(__uint_as_float(x)));
    return r;
}

static __device__ __forceinline__ void mma8(float* c,
    unsigned a0, unsigned a1, unsigned a2, unsigned a3,
    unsigned b0, unsigned b1) {
    asm volatile(
        "mma.sync.aligned.m16n8k8.row.col.f32.tf32.tf32.f32 "
        "{%0,%1,%2,%3},{%4,%5,%6,%7},{%8,%9},{%0,%1,%2,%3};"
        : "+f"(c[0]), "+f"(c[1]), "+f"(c[2]), "+f"(c[3])
        : "r"(a0), "r"(a1), "r"(a2), "r"(a3), "r"(b0), "r"(b1));
}

static __device__ __forceinline__ void cpa16(float* dst, const float* src) {
    unsigned d = (unsigned)__cvta_generic_to_shared(dst);
    asm volatile("cp.async.cg.shared.global [%0], [%1], 16;" :: "r"(d), "l"(src) : "memory");
}
#define CPA_COMMIT() asm volatile("cp.async.commit_group;" ::: "memory")
#define CPA_WAIT1()  asm volatile("cp.async.wait_group 1;" ::: "memory")

// ---------------------------------------------------------------------------
// Tile compute on one K=16 stage.
// A smem: [rows][20] row-major (k contiguous), conflict-free for ldmatrix.
// B smem: [16][136] k-major rows, conflict-free for scalar fragment loads.
// MF m16-tiles, NF n8-tiles per warp. CVT: convert raw fp32 -> tf32 in regs.
// ---------------------------------------------------------------------------
template <int MF, int NF, bool CVT>
static __device__ __forceinline__ void tile_compute(
    const float* As, const float* Bs, int mOff, int nOff, float acc[][4]) {
    const int lane = threadIdx.x & 31;
    const int g = lane >> 2, t = lane & 3;
    const int rowSel = (lane & 7) + (lane & 8);      // 0..15
    const int colSel = (lane & 16) >> 2;             // 0 or 4
    const unsigned aBase = (unsigned)__cvta_generic_to_shared(As);
    #pragma unroll
    for (int ks = 0; ks < 16; ks += 8) {
        unsigned a[MF][4];
        #pragma unroll
        for (int mf = 0; mf < MF; mf++) {
            unsigned ad = aBase + 4u * (unsigned)((mOff + mf * 16 + rowSel) * 20 + ks + colSel);
            asm volatile("ldmatrix.sync.aligned.m8n8.x4.shared.b16 {%0,%1,%2,%3}, [%4];"
                : "=r"(a[mf][0]), "=r"(a[mf][1]), "=r"(a[mf][2]), "=r"(a[mf][3])
                : "r"(ad));
        }
        if (CVT) {
            #pragma unroll
            for (int mf = 0; mf < MF; mf++)
                #pragma unroll
                for (int i = 0; i < 4; i++) a[mf][i] = cvt_tf_u(a[mf][i]);
        }
        unsigned b[NF][2];
        #pragma unroll
        for (int nf = 0; nf < NF; nf++) {
            const float* bp = Bs + (ks + t) * 136 + nOff + nf * 8 + g;
            b[nf][0] = __float_as_uint(bp[0]);
            b[nf][1] = __float_as_uint(bp[4 * 136]);
            if (CVT) { b[nf][0] = cvt_tf_u(b[nf][0]); b[nf][1] = cvt_tf_u(b[nf][1]); }
        }
        #pragma unroll
        for (int nf = 0; nf < NF; nf++)
            #pragma unroll
            for (int mf = 0; mf < MF; mf++)
                mma8(acc[mf * NF + nf], a[mf][0], a[mf][1], a[mf][2], a[mf][3],
                     b[nf][0], b[nf][1]);
    }
}

// ---------------------------------------------------------------------------
// K1: decode option (int64 vs int32) + histogram + offsets. One block.
// ---------------------------------------------------------------------------
__global__ void k_prep(const int* __restrict__ opt_raw) {
    __shared__ int s_counts[64];
    __shared__ int s_flag;
    const int tid = threadIdx.x;
    if (tid == 0) s_flag = 0;
    if (tid < 64) s_counts[tid] = 0;
    __syncthreads();
    int nz = 0;
    for (int w = 1 + 2 * tid; w < 4096; w += 512) nz |= opt_raw[w];
    if (nz) atomicOr(&s_flag, 1);
    __syncthreads();
    const bool is64 = (s_flag == 0);
    for (int i = tid; i < 4096; i += 256) {
        int v = is64 ? opt_raw[2 * i] : opt_raw[i];
        g_opt[i] = v;
        atomicAdd(&s_counts[v], 1);
    }
    __syncthreads();
    if (tid == 0) {
        int acc = 0;
        for (int c = 0; c < 64; c++) {
            g_offsets[c] = acc;
            g_cursor[c]  = acc;
            acc += s_counts[c];
        }
        g_offsets[64] = acc;
    }
}

__global__ void k_scatter() {
    const int i = blockIdx.x * 256 + threadIdx.x;
    if (i < 4096) {
        const int v = g_opt[i];
        const int p = atomicAdd(&g_cursor[v], 1);
        g_perm[p] = i;
    }
}

// Dynamic smem partition: A stages then B stages.
#define A_STAGE (128 * 20)
#define B_STAGE (16 * 136)
#define SMEM_BYTES ((A_STAGE + B_STAGE) * 3 * 4)

// ---------------------------------------------------------------------------
// GEMM1: [4096x576] @ [576x2048] + bias, relu -> g_H
// ---------------------------------------------------------------------------
__global__ __launch_bounds__(256, 2) void k_gemm1(
    const float* __restrict__ state, const float* __restrict__ embed,
    const float* __restrict__ Wx1, const float* __restrict__ bx1,
    const float* __restrict__ Wy1, const float* __restrict__ by1) {
    const int bm = blockIdx.y * 128, bnG = blockIdx.x * 128;
    const float* W; const float* bias; int bn;
    if (bnG < 1024) { W = Wx1; bias = bx1; bn = bnG; }
    else            { W = Wy1; bias = by1; bn = bnG - 1024; }

    extern __shared__ float smem[];
    float* Asm = smem;                   // 3 stages of 128x20
    float* Bsm = smem + 3 * A_STAGE;     // 3 stages of 16x136

    const int tid = threadIdx.x;
    const int warp = tid >> 5;
    const int mOff = (warp >> 2) * 64, nOff = (warp & 3) * 32;
    const int aRow = tid >> 1, aC = (tid & 1) * 8;
    const int bRow = tid >> 4, bC = (tid & 15) * 8;

    const int grow = bm + aRow;
    const float* aState = state + (size_t)grow * 512;
    const float* aEmb   = embed + g_opt[grow] * 64;

    float acc[16][4];
    #pragma unroll
    for (int i = 0; i < 16; i++)
        #pragma unroll
        for (int j = 0; j < 4; j++) acc[i][j] = 0.f;

    auto issue = [&](int stage, int k0) {
        const int gk = k0 + aC;
        const float* sa = (gk < 512) ? (aState + gk) : (aEmb + (gk - 512));
        float* ad = Asm + stage * A_STAGE + aRow * 20 + aC;
        cpa16(ad, sa); cpa16(ad + 4, sa + 4);
        const float* sb = W + (size_t)(k0 + bRow) * 1024 + bn + bC;
        float* bd = Bsm + stage * B_STAGE + bRow * 136 + bC;
        cpa16(bd, sb); cpa16(bd + 4, sb + 4);
    };

    const int NC = 36;
    issue(0, 0);  CPA_COMMIT();
    issue(1, 16); CPA_COMMIT();
    for (int c = 0; c < NC; c++) {
        CPA_WAIT1();
        __syncthreads();
        if (c + 2 < NC) issue((c + 2) % 3, (c + 2) * 16);
        CPA_COMMIT();
        tile_compute<4, 4, true>(Asm + (c % 3) * A_STAGE, Bsm + (c % 3) * B_STAGE,
                                 mOff, nOff, acc);
    }

    const int lane = tid & 31, g = lane >> 2, t = lane & 3;
    #pragma unroll
    for (int mf = 0; mf < 4; mf++)
        #pragma unroll
        for (int nf = 0; nf < 4; nf++) {
            const float* ca = acc[mf * 4 + nf];
            const int ncol = nOff + nf * 8 + 2 * t;
            const float bv0 = bias[bn + ncol], bv1 = bias[bn + ncol + 1];
            const int r0 = bm + mOff + mf * 16 + g;
            float2 o;
            o.x = fmaxf(ca[0] + bv0, 0.f); o.y = fmaxf(ca[1] + bv1, 0.f);
            *(float2*)&g_H[(size_t)r0 * 2048 + bnG + ncol] = o;
            o.x = fmaxf(ca[2] + bv0, 0.f); o.y = fmaxf(ca[3] + bv1, 0.f);
            *(float2*)&g_H[(size_t)(r0 + 8) * 2048 + bnG + ncol] = o;
        }
}

// ---------------------------------------------------------------------------
// GEMM2: cls = H @ [Wx2|Wy2] + bias (K=1024)
// ---------------------------------------------------------------------------
__global__ __launch_bounds__(256, 2) void k_gemm2(
    const float* __restrict__ Wx2, const float* __restrict__ bx2,
    const float* __restrict__ Wy2, const float* __restrict__ by2) {
    const int bm = blockIdx.y * 128, bnG = blockIdx.x * 128;
    const float* W; const float* bias; int bn, aOff;
    if (bnG < 256) { W = Wx2; bias = bx2; bn = bnG;       aOff = 0;    }
    else           { W = Wy2; bias = by2; bn = bnG - 256; aOff = 1024; }

    extern __shared__ float smem[];
    float* Asm = smem;
    float* Bsm = smem + 3 * A_STAGE;

    const int tid = threadIdx.x;
    const int warp = tid >> 5;
    const int mOff = (warp >> 2) * 64, nOff = (warp & 3) * 32;
    const int aRow = tid >> 1, aC = (tid & 1) * 8;
    const int bRow = tid >> 4, bC = (tid & 15) * 8;

    const float* aPtr = g_H + (size_t)(bm + aRow) * 2048 + aOff;

    float acc[16][4];
    #pragma unroll
    for (int i = 0; i < 16; i++)
        #pragma unroll
        for (int j = 0; j < 4; j++) acc[i][j] = 0.f;

    auto issue = [&](int stage, int k0) {
        const float* sa = aPtr + k0 + aC;
        float* ad = Asm + stage * A_STAGE + aRow * 20 + aC;
        cpa16(ad, sa); cpa16(ad + 4, sa + 4);
        const float* sb = W + (size_t)(k0 + bRow) * 256 + bn + bC;
        float* bd = Bsm + stage * B_STAGE + bRow * 136 + bC;
        cpa16(bd, sb); cpa16(bd + 4, sb + 4);
    };

    const int NC = 64;
    issue(0, 0);  CPA_COMMIT();
    issue(1, 16); CPA_COMMIT();
    for (int c = 0; c < NC; c++) {
        CPA_WAIT1();
        __syncthreads();
        if (c + 2 < NC) issue((c + 2) % 3, (c + 2) * 16);
        CPA_COMMIT();
        tile_compute<4, 4, true>(Asm + (c % 3) * A_STAGE, Bsm + (c % 3) * B_STAGE,
                                 mOff, nOff, acc);
    }

    const int lane = tid & 31, g = lane >> 2, t = lane & 3;
    #pragma unroll
    for (int mf = 0; mf < 4; mf++)
        #pragma unroll
        for (int nf = 0; nf < 4; nf++) {
            const float* ca = acc[mf * 4 + nf];
            const int ncol = nOff + nf * 8 + 2 * t;
            const float bv0 = bias[bn + ncol], bv1 = bias[bn + ncol + 1];
            const int r0 = bm + mOff + mf * 16 + g;
            *(float2*)&g_cls[(size_t)r0 * 512 + bnG + ncol] =
                make_float2(ca[0] + bv0, ca[1] + bv1);
            *(float2*)&g_cls[(size_t)(r0 + 8) * 512 + bnG + ncol] =
                make_float2(ca[2] + bv0, ca[3] + bv1);
        }
}

// ---------------------------------------------------------------------------
// GEMM_X: out_X = cls_X @ NX (M=4096,N=256,K=256)
// ---------------------------------------------------------------------------
__global__ __launch_bounds__(256, 2) void k_gemmx(
    const float* __restrict__ NX, float* __restrict__ out) {
    const int bm = blockIdx.y * 128, bn = blockIdx.x * 128;

    extern __shared__ float smem[];
    float* Asm = smem;
    float* Bsm = smem + 3 * A_STAGE;

    const int tid = threadIdx.x;
    const int warp = tid >> 5;
    const int mOff = (warp >> 2) * 64, nOff = (warp & 3) * 32;
    const int aRow = tid >> 1, aC = (tid & 1) * 8;
    const int bRow = tid >> 4, bC = (tid & 15) * 8;

    const float* aPtr = g_cls + (size_t)(bm + aRow) * 512;

    float acc[16][4];
    #pragma unroll
    for (int i = 0; i < 16; i++)
        #pragma unroll
        for (int j = 0; j < 4; j++) acc[i][j] = 0.f;

    auto issue = [&](int stage, int k0) {
        const float* sa = aPtr + k0 + aC;
        float* ad = Asm + stage * A_STAGE + aRow * 20 + aC;
        cpa16(ad, sa); cpa16(ad + 4, sa + 4);
        const float* sb = NX + (size_t)(k0 + bRow) * 256 + bn + bC;
        float* bd = Bsm + stage * B_STAGE + bRow * 136 + bC;
        cpa16(bd, sb); cpa16(bd + 4, sb + 4);
    };

    const int NC = 16;
    issue(0, 0);  CPA_COMMIT();
    issue(1, 16); CPA_COMMIT();
    for (int c = 0; c < NC; c++) {
        CPA_WAIT1();
        __syncthreads();
        if (c + 2 < NC) issue((c + 2) % 3, (c + 2) * 16);
        CPA_COMMIT();
        tile_compute<4, 4, true>(Asm + (c % 3) * A_STAGE, Bsm + (c % 3) * B_STAGE,
                                 mOff, nOff, acc);
    }

    const int lane = tid & 31, g = lane >> 2, t = lane & 3;
    #pragma unroll
    for (int mf = 0; mf < 4; mf++)
        #pragma unroll
        for (int nf = 0; nf < 4; nf++) {
            const float* ca = acc[mf * 4 + nf];
            const int ncol = nOff + nf * 8 + 2 * t;
            const int r0 = bm + mOff + mf * 16 + g;
            *(float2*)&out[(size_t)r0 * 256 + bn + ncol] = make_float2(ca[0], ca[1]);
            *(float2*)&out[(size_t)(r0 + 8) * 256 + bn + ncol] = make_float2(ca[2], ca[3]);
        }
}

// ---------------------------------------------------------------------------
// GEMM_Y (grouped by option): 64-row chunks per class. Reg-staged double
// buffer (cvt at deposit), ldmatrix fragment reads (CVT=false).
// Block 64x128: warps 2m x 4n, warp tile 32x32.
// ---------------------------------------------------------------------------
__global__ __launch_bounds__(256, 2) void k_gemmy(
    const float* __restrict__ NY, float* __restrict__ outY) {
    const int cls = blockIdx.y;
    const int bn  = blockIdx.x * 128;
    const int start = g_offsets[cls], end = g_offsets[cls + 1];
    const float* Bmat = NY + (size_t)cls * 65536;

    __shared__ float As[2][64 * 20];
    __shared__ float Bs[2][16 * 136];
    __shared__ int rowIdx[64];

    const int tid = threadIdx.x;
    const int warp = tid >> 5;
    const int mOff = (warp >> 2) * 32, nOff = (warp & 3) * 32;
    const int aRow = tid >> 2, aC = (tid & 3) * 4;
    const int bRow = tid >> 4, bC = (tid & 15) * 8;
    const int lane = tid & 31, g = lane >> 2, t = lane & 3;

    for (int chunk = start; chunk < end; chunk += 64) {
        if (tid < 64) rowIdx[tid] = (chunk + tid < end) ? g_perm[chunk + tid] : -1;
        __syncthreads();

        float acc[8][4];
        #pragma unroll
        for (int i = 0; i < 8; i++)
            #pragma unroll
            for (int j = 0; j < 4; j++) acc[i][j] = 0.f;

        float4 pa, pb0, pb1;
        const int myRow = rowIdx[aRow];
        auto fetch = [&](int k0) {
            pa = make_float4(0.f, 0.f, 0.f, 0.f);
            if (myRow >= 0)
                pa = *(const float4*)(g_cls + (size_t)myRow * 512 + 256 + k0 + aC);
            const float* sb = Bmat + (size_t)(k0 + bRow) * 256 + bn + bC;
            pb0 = *(const float4*)sb; pb1 = *(const float4*)(sb + 4);
        };
        auto deposit = [&](int buf) {
            float* ad = &As[buf][aRow * 20 + aC];
            ad[0] = f2tf(pa.x); ad[1] = f2tf(pa.y); ad[2] = f2tf(pa.z); ad[3] = f2tf(pa.w);
            float* bd = &Bs[buf][bRow * 136 + bC];
            bd[0] = f2tf(pb0.x); bd[1] = f2tf(pb0.y); bd[2] = f2tf(pb0.z); bd[3] = f2tf(pb0.w);
            bd[4] = f2tf(pb1.x); bd[5] = f2tf(pb1.y); bd[6] = f2tf(pb1.z); bd[7] = f2tf(pb1.w);
        };

        fetch(0); deposit(0); __syncthreads();
        const int NC = 16;
        for (int c = 0; c < NC; c++) {
            if (c + 1 < NC) fetch((c + 1) * 16);
            tile_compute<2, 4, false>(As[c & 1], Bs[c & 1], mOff, nOff, acc);
            if (c + 1 < NC) deposit((c + 1) & 1);
            __syncthreads();
        }

        #pragma unroll
        for (int mf = 0; mf < 2; mf++)
            #pragma unroll
            for (int nf = 0; nf < 4; nf++) {
                const float* ca = acc[mf * 4 + nf];
                const int ncol = bn + nOff + nf * 8 + 2 * t;
                const int lr = mOff + mf * 16 + g;
                const int r0 = rowIdx[lr], r1 = rowIdx[lr + 8];
                if (r0 >= 0)
                    *(float2*)&outY[(size_t)r0 * 256 + ncol] = make_float2(ca[0], ca[1]);
                if (r1 >= 0)
                    *(float2*)&outY[(size_t)r1 * 256 + ncol] = make_float2(ca[2], ca[3]);
            }
        __syncthreads();
    }
}

// ---------------------------------------------------------------------------
// Launch. Inputs: 0 state, 1 option, 2 embed, 3 Wx1, 4 bx1, 5 Wx2, 6 bx2,
// 7 Wy1, 8 by1, 9 Wy2, 10 by2, 11 NX, 12 NY. Output: [out_X | out_Y] fp32.
// ---------------------------------------------------------------------------
extern "C" void kernel_launch(void* const* d_in, const int* in_sizes, int n_in,
                              void* d_out, int out_size) {
    const float* state  = (const float*)d_in[0];
    const int*   optraw = (const int*)d_in[1];
    const float* embed  = (const float*)d_in[2];
    const float* Wx1 = (const float*)d_in[3];
    const float* bx1 = (const float*)d_in[4];
    const float* Wx2 = (const float*)d_in[5];
    const float* bx2 = (const float*)d_in[6];
    const float* Wy1 = (const float*)d_in[7];
    const float* by1 = (const float*)d_in[8];
    const float* Wy2 = (const float*)d_in[9];
    const float* by2 = (const float*)d_in[10];
    const float* NX  = (const float*)d_in[11];
    const float* NY  = (const float*)d_in[12];
    float* out = (float*)d_out;

    // >48KB dynamic smem needs an explicit opt-in (idempotent; no allocation).
    cudaFuncSetAttribute(k_gemm1, cudaFuncAttributeMaxDynamicSharedMemorySize, SMEM_BYTES);
    cudaFuncSetAttribute(k_gemm2, cudaFuncAttributeMaxDynamicSharedMemorySize, SMEM_BYTES);
    cudaFuncSetAttribute(k_gemmx, cudaFuncAttributeMaxDynamicSharedMemorySize, SMEM_BYTES);

    k_prep<<<1, 256>>>(optraw);
    k_scatter<<<16, 256>>>();
    k_gemm1<<<dim3(16, 32), 256, SMEM_BYTES>>>(state, embed, Wx1, bx1, Wy1, by1);
    k_gemm2<<<dim3(4, 32), 256, SMEM_BYTES>>>(Wx2, bx2, Wy2, by2);
    k_gemmx<<<dim3(2, 32), 256, SMEM_BYTES>>>(NX, out);
    k_gemmy<<<dim3(2, 64), 256>>>(NY, out + (size_t)4096 * 256);
}

// round 9
// speedup vs baseline: 3.1345x; 1.0955x over previous
#include <cuda_runtime.h>

// ---------------------------------------------------------------------------
// B=4096, FEAT=512, EMB=64, HID=1024, NUM_CLASSES=64, LIB=256, OUT_J=256
//   all_state = concat(state, embed[option])            [4096,576]
//   H  = relu(all_state @ [Wx1|Wy1] + b)                [4096,2048]
//   cls = H_x @ Wx2 + bx2 ; H_y @ Wy2 + by2             [4096,512]
//   out_X = cls_X @ NX ; out_Y[b] = cls_Y[b] @ NY[opt]  [4096,256] each
// tf32 mma m16n8k8. All operands pre-rounded to tf32 (cvt out of hot loops).
// ---------------------------------------------------------------------------

__device__ float g_H[4096 * 2048];      // tf32-rounded
__device__ float g_cls[4096 * 512];     // tf32-rounded
__device__ float g_state[4096 * 512];   // tf32-rounded copies
__device__ float g_emb[64 * 64];
__device__ float g_W1[576 * 2048];      // [k][ Wx1 | Wy1 ]
__device__ float g_W2[1024 * 512];      // [k][ Wx2 | Wy2 ]
__device__ float g_NX[256 * 256];
__device__ int   g_opt[4096];
__device__ int   g_offsets[65];
__device__ int   g_perm[4096];

static __device__ __forceinline__ float f2tf(float x) {
    unsigned r;
    asm("cvt.rna.tf32.f32 %0, %1;" : "=r"(r) : "f"(x));
    return __uint_as_float(r);
}
static __device__ __forceinline__ float4 tf4(float4 v) {
    v.x = f2tf(v.x); v.y = f2tf(v.y); v.z = f2tf(v.z); v.w = f2tf(v.w);
    return v;
}

static __device__ __forceinline__ void mma8(float* c,
    unsigned a0, unsigned a1, unsigned a2, unsigned a3,
    unsigned b0, unsigned b1) {
    asm volatile(
        "mma.sync.aligned.m16n8k8.row.col.f32.tf32.tf32.f32 "
        "{%0,%1,%2,%3},{%4,%5,%6,%7},{%8,%9},{%0,%1,%2,%3};"
        : "+f"(c[0]), "+f"(c[1]), "+f"(c[2]), "+f"(c[3])
        : "r"(a0), "r"(a1), "r"(a2), "r"(a3), "r"(b0), "r"(b1));
}

static __device__ __forceinline__ void cpa16(float* dst, const float* src) {
    unsigned d = (unsigned)__cvta_generic_to_shared(dst);
    asm volatile("cp.async.cg.shared.global [%0], [%1], 16;" :: "r"(d), "l"(src) : "memory");
}
#define CPA_COMMIT() asm volatile("cp.async.commit_group;" ::: "memory")
#define CPA_WAIT1()  asm volatile("cp.async.wait_group 1;" ::: "memory")

// ---------------------------------------------------------------------------
// Tile compute, one K=16 stage. A smem [rows][20] (k contig), B smem [16][136].
// All smem data already tf32-rounded. MF m16-frags, NF n8-frags per warp.
// ---------------------------------------------------------------------------
template <int MF, int NF>
static __device__ __forceinline__ void tile_compute(
    const float* As, const float* Bs, int mOff, int nOff, float acc[][4]) {
    const int lane = threadIdx.x & 31;
    const int g = lane >> 2, t = lane & 3;
    const int rowSel = (lane & 7) + (lane & 8);
    const int colSel = (lane & 16) >> 2;
    const unsigned aBase = (unsigned)__cvta_generic_to_shared(As);
    #pragma unroll
    for (int ks = 0; ks < 16; ks += 8) {
        unsigned a[MF][4];
        #pragma unroll
        for (int mf = 0; mf < MF; mf++) {
            unsigned ad = aBase + 4u * (unsigned)((mOff + mf * 16 + rowSel) * 20 + ks + colSel);
            asm volatile("ldmatrix.sync.aligned.m8n8.x4.shared.b16 {%0,%1,%2,%3}, [%4];"
                : "=r"(a[mf][0]), "=r"(a[mf][1]), "=r"(a[mf][2]), "=r"(a[mf][3])
                : "r"(ad));
        }
        unsigned b[NF][2];
        #pragma unroll
        for (int nf = 0; nf < NF; nf++) {
            const float* bp = Bs + (ks + t) * 136 + nOff + nf * 8 + g;
            b[nf][0] = __float_as_uint(bp[0]);
            b[nf][1] = __float_as_uint(bp[4 * 136]);
        }
        #pragma unroll
        for (int nf = 0; nf < NF; nf++)
            #pragma unroll
            for (int mf = 0; mf < MF; mf++)
                mma8(acc[mf * NF + nf], a[mf][0], a[mf][1], a[mf][2], a[mf][3],
                     b[nf][0], b[nf][1]);
    }
}

// ---------------------------------------------------------------------------
// k_cvtprep: block 0 = option decode + histogram + offsets + scatter.
// blocks 1..N = tf32 pre-conversion of state/embed/W1/W2/NX (float4 grid-stride).
// ---------------------------------------------------------------------------
#define R0_END 524288    // state       4096*512/4
#define R1_END 525312    // embed       +64*64/4
#define R2_END 820224    // W1          +576*2048/4
#define R3_END 951296    // W2          +1024*512/4
#define R4_END 967680    // NX          +256*256/4

__global__ void k_cvtprep(
    const float* __restrict__ state, const float* __restrict__ embed,
    const float* __restrict__ Wx1, const float* __restrict__ Wy1,
    const float* __restrict__ Wx2, const float* __restrict__ Wy2,
    const float* __restrict__ NX, const int* __restrict__ opt_raw) {
    const int tid = threadIdx.x;
    if (blockIdx.x == 0) {
        __shared__ int s_counts[64];
        __shared__ int s_cursor[64];
        __shared__ int s_flag;
        if (tid == 0) s_flag = 0;
        if (tid < 64) s_counts[tid] = 0;
        __syncthreads();
        int nz = 0;
        for (int w = 1 + 2 * tid; w < 4096; w += 512) nz |= opt_raw[w];
        if (nz) atomicOr(&s_flag, 1);
        __syncthreads();
        const bool is64 = (s_flag == 0);
        for (int i = tid; i < 4096; i += 256) {
            int v = is64 ? opt_raw[2 * i] : opt_raw[i];
            g_opt[i] = v;
            atomicAdd(&s_counts[v], 1);
        }
        __syncthreads();
        if (tid == 0) {
            int acc = 0;
            for (int c = 0; c < 64; c++) {
                g_offsets[c] = acc;
                s_cursor[c]  = acc;
                acc += s_counts[c];
            }
            g_offsets[64] = acc;
        }
        __syncthreads();
        for (int i = tid; i < 4096; i += 256) {
            const int v = g_opt[i];
            const int p = atomicAdd(&s_cursor[v], 1);
            g_perm[p] = i;
        }
        return;
    }
    const int nb = gridDim.x - 1;
    for (long i = (long)(blockIdx.x - 1) * 256 + tid; i < R4_END; i += (long)nb * 256) {
        if (i < R0_END) {
            ((float4*)g_state)[i] = tf4(((const float4*)state)[i]);
        } else if (i < R1_END) {
            long j = i - R0_END;
            ((float4*)g_emb)[j] = tf4(((const float4*)embed)[j]);
        } else if (i < R2_END) {
            long j = i - R1_END;
            int row = (int)(j >> 9), col = ((int)j & 511) * 4;
            const float* src = (col < 1024) ? (Wx1 + row * 1024 + col)
                                            : (Wy1 + row * 1024 + col - 1024);
            *(float4*)(g_W1 + row * 2048 + col) = tf4(*(const float4*)src);
        } else if (i < R3_END) {
            long j = i - R2_END;
            int row = (int)(j >> 7), col = ((int)j & 127) * 4;
            const float* src = (col < 256) ? (Wx2 + row * 256 + col)
                                           : (Wy2 + row * 256 + col - 256);
            *(float4*)(g_W2 + row * 512 + col) = tf4(*(const float4*)src);
        } else {
            long j = i - R3_END;
            ((float4*)g_NX)[j] = tf4(((const float4*)NX)[j]);
        }
    }
}

#define A_ST1 (128 * 20)
#define B_ST  (16 * 136)
#define SMEM1_BYTES ((A_ST1 + B_ST) * 3 * 4)

// ---------------------------------------------------------------------------
// GEMM1: [4096x576] @ g_W1[576x2048] + bias, relu -> g_H (tf32-rounded).
// 128x128 tile, 8 warps (2m x 4n of 64x32), 3-stage cp.async.
// ---------------------------------------------------------------------------
__global__ __launch_bounds__(256, 2) void k_gemm1(
    const float* __restrict__ bx1, const float* __restrict__ by1) {
    const int bm = blockIdx.y * 128, bnG = blockIdx.x * 128;
    const float* bias = (bnG < 1024) ? bx1 : by1;
    const int bn = bnG & 1023;

    extern __shared__ float smem[];
    float* Asm = smem;
    float* Bsm = smem + 3 * A_ST1;

    const int tid = threadIdx.x;
    const int warp = tid >> 5;
    const int mOff = (warp >> 2) * 64, nOff = (warp & 3) * 32;
    const int aRow = tid >> 1, aC = (tid & 1) * 8;
    const int bRow = tid >> 4, bC = (tid & 15) * 8;

    const int grow = bm + aRow;
    const float* aState = g_state + (size_t)grow * 512;
    const float* aEmb   = g_emb + g_opt[grow] * 64;

    float acc[16][4];
    #pragma unroll
    for (int i = 0; i < 16; i++)
        #pragma unroll
        for (int j = 0; j < 4; j++) acc[i][j] = 0.f;

    auto issue = [&](int stage, int k0) {
        const int gk = k0 + aC;
        const float* sa = (gk < 512) ? (aState + gk) : (aEmb + (gk - 512));
        float* ad = Asm + stage * A_ST1 + aRow * 20 + aC;
        cpa16(ad, sa); cpa16(ad + 4, sa + 4);
        const float* sb = g_W1 + (size_t)(k0 + bRow) * 2048 + bnG + bC;
        float* bd = Bsm + stage * B_ST + bRow * 136 + bC;
        cpa16(bd, sb); cpa16(bd + 4, sb + 4);
    };

    const int NC = 36;
    issue(0, 0);  CPA_COMMIT();
    issue(1, 16); CPA_COMMIT();
    for (int c = 0; c < NC; c++) {
        CPA_WAIT1();
        __syncthreads();
        if (c + 2 < NC) issue((c + 2) % 3, (c + 2) * 16);
        CPA_COMMIT();
        tile_compute<4, 4>(Asm + (c % 3) * A_ST1, Bsm + (c % 3) * B_ST,
                           mOff, nOff, acc);
    }

    const int lane = tid & 31, g = lane >> 2, t = lane & 3;
    #pragma unroll
    for (int mf = 0; mf < 4; mf++)
        #pragma unroll
        for (int nf = 0; nf < 4; nf++) {
            const float* ca = acc[mf * 4 + nf];
            const int ncol = nOff + nf * 8 + 2 * t;
            const float bv0 = bias[bn + ncol], bv1 = bias[bn + ncol + 1];
            const int r0 = bm + mOff + mf * 16 + g;
            float2 o;
            o.x = f2tf(fmaxf(ca[0] + bv0, 0.f)); o.y = f2tf(fmaxf(ca[1] + bv1, 0.f));
            *(float2*)&g_H[(size_t)r0 * 2048 + bnG + ncol] = o;
            o.x = f2tf(fmaxf(ca[2] + bv0, 0.f)); o.y = f2tf(fmaxf(ca[3] + bv1, 0.f));
            *(float2*)&g_H[(size_t)(r0 + 8) * 2048 + bnG + ncol] = o;
        }
}

// ---------------------------------------------------------------------------
// GEMM2: cls = H @ g_W2 + bias (K=1024). 64x128 tile -> 256 blocks (fills chip).
// 8 warps (2m x 4n of 32x32). 3-stage cp.async, static smem.
// ---------------------------------------------------------------------------
__global__ __launch_bounds__(256, 2) void k_gemm2(
    const float* __restrict__ bx2, const float* __restrict__ by2) {
    const int bm = blockIdx.y * 64, bnG = blockIdx.x * 128;
    const float* bias = (bnG < 256) ? bx2 : by2;
    const int bn = bnG & 255;
    const int aOff = (bnG < 256) ? 0 : 1024;

    __shared__ float Asm[3 * 64 * 20];
    __shared__ float Bsm[3 * B_ST];

    const int tid = threadIdx.x;
    const int warp = tid >> 5;
    const int mOff = (warp >> 2) * 32, nOff = (warp & 3) * 32;
    const int aRow = tid >> 2, aC = (tid & 3) * 4;
    const int bRow = tid >> 4, bC = (tid & 15) * 8;

    const float* aPtr = g_H + (size_t)(bm + aRow) * 2048 + aOff;

    float acc[8][4];
    #pragma unroll
    for (int i = 0; i < 8; i++)
        #pragma unroll
        for (int j = 0; j < 4; j++) acc[i][j] = 0.f;

    auto issue = [&](int stage, int k0) {
        float* ad = Asm + stage * (64 * 20) + aRow * 20 + aC;
        cpa16(ad, aPtr + k0 + aC);
        const float* sb = g_W2 + (size_t)(k0 + bRow) * 512 + bnG + bC;
        float* bd = Bsm + stage * B_ST + bRow * 136 + bC;
        cpa16(bd, sb); cpa16(bd + 4, sb + 4);
    };

    const int NC = 64;
    issue(0, 0);  CPA_COMMIT();
    issue(1, 16); CPA_COMMIT();
    for (int c = 0; c < NC; c++) {
        CPA_WAIT1();
        __syncthreads();
        if (c + 2 < NC) issue((c + 2) % 3, (c + 2) * 16);
        CPA_COMMIT();
        tile_compute<2, 4>(Asm + (c % 3) * (64 * 20), Bsm + (c % 3) * B_ST,
                           mOff, nOff, acc);
    }

    const int lane = tid & 31, g = lane >> 2, t = lane & 3;
    #pragma unroll
    for (int mf = 0; mf < 2; mf++)
        #pragma unroll
        for (int nf = 0; nf < 4; nf++) {
            const float* ca = acc[mf * 4 + nf];
            const int ncol = nOff + nf * 8 + 2 * t;
            const float bv0 = bias[bn + ncol], bv1 = bias[bn + ncol + 1];
            const int r0 = bm + mOff + mf * 16 + g;
            *(float2*)&g_cls[(size_t)r0 * 512 + bnG + ncol] =
                make_float2(f2tf(ca[0] + bv0), f2tf(ca[1] + bv1));
            *(float2*)&g_cls[(size_t)(r0 + 8) * 512 + bnG + ncol] =
                make_float2(f2tf(ca[2] + bv0), f2tf(ca[3] + bv1));
        }
}

// ---------------------------------------------------------------------------
// GEMM X+Y fused launch (192 blocks).
//   blocks [0,64):  out_X = cls_X @ g_NX   (128x128 tiles)
//   blocks [64,192): grouped out_Y per class (64-row chunks x 128 cols)
// ---------------------------------------------------------------------------
__global__ __launch_bounds__(256, 2) void k_gemmxy(
    const float* __restrict__ NY, float* __restrict__ out) {
    extern __shared__ float smem[];
    const int tid = threadIdx.x;
    const int warp = tid >> 5;
    const int lane = tid & 31, g = lane >> 2, t = lane & 3;

    if (blockIdx.x < 64) {
        // ----- X path -----
        const int bm = (blockIdx.x >> 1) * 128, bn = (blockIdx.x & 1) * 128;
        float* Asm = smem;
        float* Bsm = smem + 3 * A_ST1;
        const int mOff = (warp >> 2) * 64, nOff = (warp & 3) * 32;
        const int aRow = tid >> 1, aC = (tid & 1) * 8;
        const int bRow = tid >> 4, bC = (tid & 15) * 8;
        const float* aPtr = g_cls + (size_t)(bm + aRow) * 512;

        float acc[16][4];
        #pragma unroll
        for (int i = 0; i < 16; i++)
            #pragma unroll
            for (int j = 0; j < 4; j++) acc[i][j] = 0.f;

        auto issue = [&](int stage, int k0) {
            float* ad = Asm + stage * A_ST1 + aRow * 20 + aC;
            cpa16(ad, aPtr + k0 + aC); cpa16(ad + 4, aPtr + k0 + aC + 4);
            const float* sb = g_NX + (size_t)(k0 + bRow) * 256 + bn + bC;
            float* bd = Bsm + stage * B_ST + bRow * 136 + bC;
            cpa16(bd, sb); cpa16(bd + 4, sb + 4);
        };

        const int NC = 16;
        issue(0, 0);  CPA_COMMIT();
        issue(1, 16); CPA_COMMIT();
        for (int c = 0; c < NC; c++) {
            CPA_WAIT1();
            __syncthreads();
            if (c + 2 < NC) issue((c + 2) % 3, (c + 2) * 16);
            CPA_COMMIT();
            tile_compute<4, 4>(Asm + (c % 3) * A_ST1, Bsm + (c % 3) * B_ST,
                               mOff, nOff, acc);
        }
        #pragma unroll
        for (int mf = 0; mf < 4; mf++)
            #pragma unroll
            for (int nf = 0; nf < 4; nf++) {
                const float* ca = acc[mf * 4 + nf];
                const int ncol = nOff + nf * 8 + 2 * t;
                const int r0 = bm + mOff + mf * 16 + g;
                *(float2*)&out[(size_t)r0 * 256 + bn + ncol] = make_float2(ca[0], ca[1]);
                *(float2*)&out[(size_t)(r0 + 8) * 256 + bn + ncol] = make_float2(ca[2], ca[3]);
            }
    } else {
        // ----- Y path -----
        float* outY = out + (size_t)4096 * 256;
        const int yb = blockIdx.x - 64;
        const int cls = yb >> 1;
        const int bn  = (yb & 1) * 128;
        const int start = g_offsets[cls], end = g_offsets[cls + 1];
        const float* Bmat = NY + (size_t)cls * 65536;

        float* AsY = smem;                    // 2 x 64*20
        float* BsY = smem + 2 * (64 * 20);    // 2 x 16*136
        int* rowIdx = (int*)(smem + 2 * (64 * 20) + 2 * B_ST);

        const int mOff = (warp >> 2) * 32, nOff = (warp & 3) * 32;
        const int aRow = tid >> 2, aC = (tid & 3) * 4;
        const int bRow = tid >> 4, bC = (tid & 15) * 8;

        for (int chunk = start; chunk < end; chunk += 64) {
            if (tid < 64) rowIdx[tid] = (chunk + tid < end) ? g_perm[chunk + tid] : -1;
            __syncthreads();

            float acc[8][4];
            #pragma unroll
            for (int i = 0; i < 8; i++)
                #pragma unroll
                for (int j = 0; j < 4; j++) acc[i][j] = 0.f;

            float4 pa, pb0, pb1;
            const int myRow = rowIdx[aRow];
            auto fetch = [&](int k0) {
                pa = make_float4(0.f, 0.f, 0.f, 0.f);
                if (myRow >= 0)
                    pa = *(const float4*)(g_cls + (size_t)myRow * 512 + 256 + k0 + aC);
                const float* sb = Bmat + (size_t)(k0 + bRow) * 256 + bn + bC;
                pb0 = *(const float4*)sb; pb1 = *(const float4*)(sb + 4);
            };
            auto deposit = [&](int buf) {
                float* ad = AsY + buf * (64 * 20) + aRow * 20 + aC;
                ad[0] = pa.x; ad[1] = pa.y; ad[2] = pa.z; ad[3] = pa.w;  // g_cls pre-rounded
                float* bd = BsY + buf * B_ST + bRow * 136 + bC;
                bd[0] = f2tf(pb0.x); bd[1] = f2tf(pb0.y); bd[2] = f2tf(pb0.z); bd[3] = f2tf(pb0.w);
                bd[4] = f2tf(pb1.x); bd[5] = f2tf(pb1.y); bd[6] = f2tf(pb1.z); bd[7] = f2tf(pb1.w);
            };

            fetch(0); deposit(0); __syncthreads();
            const int NC = 16;
            for (int c = 0; c < NC; c++) {
                if (c + 1 < NC) fetch((c + 1) * 16);
                tile_compute<2, 4>(AsY + (c & 1) * (64 * 20), BsY + (c & 1) * B_ST,
                                   mOff, nOff, acc);
                if (c + 1 < NC) deposit((c + 1) & 1);
                __syncthreads();
            }

            #pragma unroll
            for (int mf = 0; mf < 2; mf++)
                #pragma unroll
                for (int nf = 0; nf < 4; nf++) {
                    const float* ca = acc[mf * 4 + nf];
                    const int ncol = bn + nOff + nf * 8 + 2 * t;
                    const int lr = mOff + mf * 16 + g;
                    const int r0 = rowIdx[lr], r1 = rowIdx[lr + 8];
                    if (r0 >= 0)
                        *(float2*)&outY[(size_t)r0 * 256 + ncol] = make_float2(ca[0], ca[1]);
                    if (r1 >= 0)
                        *(float2*)&outY[(size_t)r1 * 256 + ncol] = make_float2(ca[2], ca[3]);
                }
            __syncthreads();
        }
    }
}

// ---------------------------------------------------------------------------
// Launch. Inputs: 0 state, 1 option, 2 embed, 3 Wx1, 4 bx1, 5 Wx2, 6 bx2,
// 7 Wy1, 8 by1, 9 Wy2, 10 by2, 11 NX, 12 NY. Output: [out_X | out_Y] fp32.
// ---------------------------------------------------------------------------
extern "C" void kernel_launch(void* const* d_in, const int* in_sizes, int n_in,
                              void* d_out, int out_size) {
    const float* state  = (const float*)d_in[0];
    const int*   optraw = (const int*)d_in[1];
    const float* embed  = (const float*)d_in[2];
    const float* Wx1 = (const float*)d_in[3];
    const float* bx1 = (const float*)d_in[4];
    const float* Wx2 = (const float*)d_in[5];
    const float* bx2 = (const float*)d_in[6];
    const float* Wy1 = (const float*)d_in[7];
    const float* by1 = (const float*)d_in[8];
    const float* Wy2 = (const float*)d_in[9];
    const float* by2 = (const float*)d_in[10];
    const float* NX  = (const float*)d_in[11];
    const float* NY  = (const float*)d_in[12];
    float* out = (float*)d_out;

    cudaFuncSetAttribute(k_gemm1,  cudaFuncAttributeMaxDynamicSharedMemorySize, SMEM1_BYTES);
    cudaFuncSetAttribute(k_gemmxy, cudaFuncAttributeMaxDynamicSharedMemorySize, SMEM1_BYTES);

    k_cvtprep<<<297, 256>>>(state, embed, Wx1, Wy1, Wx2, Wy2, NX, optraw);
    k_gemm1<<<dim3(16, 32), 256, SMEM1_BYTES>>>(bx1, by1);
    k_gemm2<<<dim3(4, 64), 256>>>(bx2, by2);
    k_gemmxy<<<192, 256, SMEM1_BYTES>>>(NY, out);
}